// round 12
// baseline (speedup 1.0000x reference)
#include <cuda_runtime.h>
#include <cuda_bf16.h>
#include <math.h>

#define NN     1195
#define NUSER  805
#define NITEM  390
#define BB     2048
#define KPAD   1216           // A col stride (19 tiles of 64)
#define RA     1280           // A row alloc (10 blocks of 128)
#define MATSZ  (RA*KPAD)
#define NCH    19             // split-K chunks: ONE 64-wide k-tile each
#define CHS    (3*RA*64)      // pacc chunk stride (floats)

// ---------------- packed f32x2 helpers (Blackwell FFMA2) ---------------------
__device__ __forceinline__ void fma2(unsigned long long& d,
                                     unsigned long long a, unsigned long long b){
    asm("fma.rn.f32x2 %0, %1, %2, %0;" : "+l"(d) : "l"(a), "l"(b));
}
__device__ __forceinline__ unsigned long long dupf(float x){
    unsigned long long r;
    asm("mov.b64 %0, {%1, %1};" : "=l"(r) : "f"(x));
    return r;
}
__device__ __forceinline__ float2 u2f(unsigned long long x){
    float2 r;
    asm("mov.b64 {%0, %1}, %2;" : "=f"(r.x), "=f"(r.y) : "l"(x));
    return r;
}
__device__ __forceinline__ float wredsum(float s){
    #pragma unroll
    for (int off = 16; off; off >>= 1) s += __shfl_xor_sync(0xffffffffu, s, off);
    return s;
}

// ---------------- scratch (zero-initialized at module load) ------------------
__device__ __nv_bfloat16 d_A[3*MATSZ]; // exact small-int counts; re-zeroed in k_agg<2>
__device__ float d_cnt[3*RA];         // zeroed in k_esmlp (end of run)
__device__ float d_h1[NN*64];
__device__ float d_h2[3*NN*64];
__device__ float d_pacc[NCH*CHS];     // fully overwritten each agg
__device__ float d_y2[3*NN*64];
__device__ float d_cu[NITEM*64];
__device__ float d_ci[NUSER*64];
__device__ float d_colss[3*64];       // zeroed in k_final (end of run)
__device__ float d_cssE[64];          // zeroed in k_final (end of run)
__device__ float d_hb[BB*64];
__device__ float d_bnsum[64];         // zeroed in k_build3 (start of run)
__device__ float d_bnsum2[64];

// ====== launch 1: build A (bf16 atomics) + lin1 + bn zero ====================
__global__ __launch_bounds__(256,3) void k_build3(
        const int* __restrict__ e0, int E0,
        const int* __restrict__ e1, int E1,
        const int* __restrict__ e2, int E2,
        const float* __restrict__ x, const float* __restrict__ W,
        const float* __restrict__ b){
    int g = blockIdx.y;
    int tid = threadIdx.x;
    if (g < 3){
        const int* e = (g == 0) ? e0 : (g == 1) ? e1 : e2;
        int E       = (g == 0) ? E0 : (g == 1) ? E1 : E2;
        int i = blockIdx.x*256 + tid;
        if (i < E){
            int s = e[i];
            int d = e[E + i];
            atomicAdd(&d_A[(size_t)g*MATSZ + (size_t)d*KPAD + s],
                      __float2bfloat16(1.0f));
        }
        return;
    }
    // g == 3 : auxiliary work
    if (blockIdx.x == 38){
        if (tid < 64){ d_bnsum[tid] = 0.f; d_bnsum2[tid] = 0.f; }
        return;
    }
    if (blockIdx.x > 38) return;
    // lin1: 32 rows per block
    __shared__ float Ws[64*68];
    __shared__ float xs[32*68];
    int n0 = blockIdx.x*32;
    for (int i = tid; i < 1024; i += 256)
        *reinterpret_cast<float4*>(&Ws[(i>>4)*68 + (i&15)*4]) =
            reinterpret_cast<const float4*>(W)[i];
    for (int i = tid; i < 512; i += 256){
        int r = i>>4, c4 = i&15;
        float4 v = (n0 + r < NN) ? reinterpret_cast<const float4*>(x)[(n0+r)*16 + c4]
                                 : make_float4(0,0,0,0);
        *reinterpret_cast<float4*>(&xs[r*68 + c4*4]) = v;
    }
    __syncthreads();
    int tx = tid & 63, ty = tid >> 6;
    float bb = b[tx];
    #pragma unroll
    for (int i0 = 0; i0 < 8; i0 += 2){
        int rl = ty*8 + i0;
        float a0 = bb, a1 = bb;
        #pragma unroll
        for (int k = 0; k < 64; k += 4){
            float4 w  = *reinterpret_cast<const float4*>(&Ws[tx*68 + k]);
            float4 x0 = *reinterpret_cast<const float4*>(&xs[(rl  )*68 + k]);
            float4 x1 = *reinterpret_cast<const float4*>(&xs[(rl+1)*68 + k]);
            a0 = fmaf(x0.x,w.x,a0); a0 = fmaf(x0.y,w.y,a0);
            a0 = fmaf(x0.z,w.z,a0); a0 = fmaf(x0.w,w.w,a0);
            a1 = fmaf(x1.x,w.x,a1); a1 = fmaf(x1.y,w.y,a1);
            a1 = fmaf(x1.z,w.z,a1); a1 = fmaf(x1.w,w.w,a1);
        }
        int n = n0 + rl;
        if (n     < NN) d_h1[(size_t)(n  )*64 + tx] = a0;
        if (n + 1 < NN) d_h1[(size_t)(n+1)*64 + tx] = a1;
    }
}

// ====== agg: pacc[t] = A_tile @ h (128-row x 64-col tile, 256 threads) =======
// A stored bf16 (exact small ints), converted to fp32 smem during staging.
// All 8 threads of a row-group read the SAME A values -> rsum is already the
// complete tile-row sum; tx==0 adds it directly (layer 1 only).
// Layer 2 re-zeroes its own gmem A tile (each tile read exactly once there).
template<int LAYER>
__global__ __launch_bounds__(256,3) void k_agg(){
    const int g = blockIdx.y, t = blockIdx.z;
    __nv_bfloat16* Anc = d_A + (size_t)g*MATSZ;
    const __nv_bfloat16* A = Anc;
    const float* h = (LAYER == 1) ? d_h1 : d_h2 + (size_t)g*NN*64;
    __shared__ float As[128*64];   // fp32, xor-swizzled by (row>>2)&3
    __shared__ float hs[64*64];
    int tid = threadIdx.x;
    int tx = tid & 7;              // 8 col-groups of 8
    int ty = tid >> 3;             // 0..31, 4 rows each
    int n0 = blockIdx.x*128;
    int k0 = t*64;
    // stage A: 128 rows x 64 bf16 = 16KB gmem -> fp32 smem (8 elems / 16B chunk)
    #pragma unroll
    for (int i = tid; i < 1024; i += 256){
        int r = i >> 3, c8 = i & 7;
        uint4 raw = *reinterpret_cast<const uint4*>(
                      &A[(size_t)(n0 + r)*KPAD + k0 + c8*8]);
        float2 f0 = __bfloat1622float2(*reinterpret_cast<__nv_bfloat162*>(&raw.x));
        float2 f1 = __bfloat1622float2(*reinterpret_cast<__nv_bfloat162*>(&raw.y));
        float2 f2 = __bfloat1622float2(*reinterpret_cast<__nv_bfloat162*>(&raw.z));
        float2 f3 = __bfloat1622float2(*reinterpret_cast<__nv_bfloat162*>(&raw.w));
        int sw = ((r>>2) & 3) << 3;
        int base = (c8*8) ^ sw;
        *reinterpret_cast<float4*>(&As[r*64 + base    ]) = make_float4(f0.x,f0.y,f1.x,f1.y);
        *reinterpret_cast<float4*>(&As[r*64 + base + 4]) = make_float4(f2.x,f2.y,f3.x,f3.y);
    }
    #pragma unroll
    for (int i = tid; i < 1024; i += 256){
        int jr = i >> 4, c4 = i & 15;
        int gk = k0 + jr;
        float4 v = (gk < NN) ? reinterpret_cast<const float4*>(h)[gk*16 + c4]
                             : make_float4(0,0,0,0);
        *reinterpret_cast<float4*>(&hs[jr*64 + c4*4]) = v;
    }
    __syncthreads();
    if (LAYER == 2){
        // A tile is in smem now; re-zero the gmem bf16 copy for the next replay.
        uint4 z = make_uint4(0,0,0,0);
        #pragma unroll
        for (int i = tid; i < 1024; i += 256){
            int r = i >> 3, c8 = i & 7;
            *reinterpret_cast<uint4*>(&Anc[(size_t)(n0 + r)*KPAD + k0 + c8*8]) = z;
        }
    }
    unsigned long long acc[4][4];
    #pragma unroll
    for (int r = 0; r < 4; r++){
        acc[r][0] = 0ull; acc[r][1] = 0ull; acc[r][2] = 0ull; acc[r][3] = 0ull;
    }
    float rsum[4] = {0.f, 0.f, 0.f, 0.f};
    int s8 = (ty & 3) << 3;        // 8-aligned: (j4+i)^s8 == (j4^s8)+i, i<4
    const float* Arow = &As[(ty*4)*64];
    #pragma unroll 4
    for (int j4 = 0; j4 < 64; j4 += 4){
        int jc = j4 ^ s8;
        float4 Av0 = *reinterpret_cast<const float4*>(&Arow[        jc]);
        float4 Av1 = *reinterpret_cast<const float4*>(&Arow[  64 + jc]);
        float4 Av2 = *reinterpret_cast<const float4*>(&Arow[ 128 + jc]);
        float4 Av3 = *reinterpret_cast<const float4*>(&Arow[ 192 + jc]);
        if (LAYER == 1){
            rsum[0] += Av0.x + Av0.y + Av0.z + Av0.w;
            rsum[1] += Av1.x + Av1.y + Av1.z + Av1.w;
            rsum[2] += Av2.x + Av2.y + Av2.z + Av2.w;
            rsum[3] += Av3.x + Av3.y + Av3.z + Av3.w;
        }
        #pragma unroll
        for (int jj = 0; jj < 4; jj++){
            int j = j4 + jj;
            ulonglong2 h0 = *reinterpret_cast<const ulonglong2*>(&hs[j*64 + tx*8]);
            ulonglong2 h1 = *reinterpret_cast<const ulonglong2*>(&hs[j*64 + tx*8 + 4]);
            const float* a0p = &Av0.x;
            const float* a1p = &Av1.x;
            const float* a2p = &Av2.x;
            const float* a3p = &Av3.x;
            unsigned long long a0 = dupf(a0p[jj]);
            unsigned long long a1 = dupf(a1p[jj]);
            unsigned long long a2 = dupf(a2p[jj]);
            unsigned long long a3 = dupf(a3p[jj]);
            fma2(acc[0][0], a0, h0.x); fma2(acc[0][1], a0, h0.y);
            fma2(acc[0][2], a0, h1.x); fma2(acc[0][3], a0, h1.y);
            fma2(acc[1][0], a1, h0.x); fma2(acc[1][1], a1, h0.y);
            fma2(acc[1][2], a1, h1.x); fma2(acc[1][3], a1, h1.y);
            fma2(acc[2][0], a2, h0.x); fma2(acc[2][1], a2, h0.y);
            fma2(acc[2][2], a2, h1.x); fma2(acc[2][3], a2, h1.y);
            fma2(acc[3][0], a3, h0.x); fma2(acc[3][1], a3, h0.y);
            fma2(acc[3][2], a3, h1.x); fma2(acc[3][3], a3, h1.y);
        }
    }
    float* p = d_pacc + (size_t)t*CHS + (size_t)g*RA*64;
    #pragma unroll
    for (int r = 0; r < 4; r++){
        size_t row = n0 + ty*4 + r;
        ulonglong2 v0; v0.x = acc[r][0]; v0.y = acc[r][1];
        ulonglong2 v1; v1.x = acc[r][2]; v1.y = acc[r][3];
        *reinterpret_cast<ulonglong2*>(&p[row*64 + tx*8    ]) = v0;
        *reinterpret_cast<ulonglong2*>(&p[row*64 + tx*8 + 4]) = v1;
    }
    if (LAYER == 1 && tx == 0){
        #pragma unroll
        for (int r = 0; r < 4; r++)
            atomicAdd(&d_cnt[g*RA + n0 + ty*4 + r], rsum[r]);
    }
}

// ====== fin1: y1 = tanh(ic*sum(pacc)); h2 = y1 @ W2^T + b2 ===================
__global__ __launch_bounds__(256) void k_fin1(const float* __restrict__ W2,
                                              const float* __restrict__ b2){
    int g = blockIdx.y;
    int n0 = blockIdx.x*64;
    __shared__ float Ws[64*68];
    __shared__ float ys[64*68];
    int tid = threadIdx.x;
    for (int i = tid; i < 1024; i += 256){
        int r = i>>4, c4 = i&15;
        *reinterpret_cast<float4*>(&Ws[r*68 + c4*4]) =
            reinterpret_cast<const float4*>(W2)[i];
        size_t off = ((size_t)g*RA + n0 + r)*16 + c4;
        float4 s = reinterpret_cast<const float4*>(d_pacc)[off];
        #pragma unroll
        for (int c = 1; c < NCH; c++){
            float4 v = reinterpret_cast<const float4*>(d_pacc)[(size_t)c*(CHS/4) + off];
            s.x += v.x; s.y += v.y; s.z += v.z; s.w += v.w;
        }
        float ic = 1.f / fmaxf(d_cnt[g*RA + n0 + r], 1.f);
        float4 o;
        o.x = tanhf(ic*s.x); o.y = tanhf(ic*s.y);
        o.z = tanhf(ic*s.z); o.w = tanhf(ic*s.w);
        *reinterpret_cast<float4*>(&ys[r*68 + c4*4]) = o;
    }
    __syncthreads();
    int tx = tid & 63, ty = tid >> 6;
    float bb = b2[tx];
    #pragma unroll
    for (int i0 = 0; i0 < 16; i0 += 4){
        int rl = ty*16 + i0;
        float a0 = bb, a1 = bb, a2 = bb, a3 = bb;
        #pragma unroll
        for (int k = 0; k < 64; k += 4){
            float4 w  = *reinterpret_cast<const float4*>(&Ws[tx*68 + k]);
            float4 x0 = *reinterpret_cast<const float4*>(&ys[(rl  )*68 + k]);
            float4 x1 = *reinterpret_cast<const float4*>(&ys[(rl+1)*68 + k]);
            float4 x2 = *reinterpret_cast<const float4*>(&ys[(rl+2)*68 + k]);
            float4 x3 = *reinterpret_cast<const float4*>(&ys[(rl+3)*68 + k]);
            a0 = fmaf(x0.x,w.x,a0); a0 = fmaf(x0.y,w.y,a0);
            a0 = fmaf(x0.z,w.z,a0); a0 = fmaf(x0.w,w.w,a0);
            a1 = fmaf(x1.x,w.x,a1); a1 = fmaf(x1.y,w.y,a1);
            a1 = fmaf(x1.z,w.z,a1); a1 = fmaf(x1.w,w.w,a1);
            a2 = fmaf(x2.x,w.x,a2); a2 = fmaf(x2.y,w.y,a2);
            a2 = fmaf(x2.z,w.z,a2); a2 = fmaf(x2.w,w.w,a2);
            a3 = fmaf(x3.x,w.x,a3); a3 = fmaf(x3.y,w.y,a3);
            a3 = fmaf(x3.z,w.z,a3); a3 = fmaf(x3.w,w.w,a3);
        }
        int n = n0 + rl;
        if (n     < NN) d_h2[((size_t)g*NN + n    )*64 + tx] = a0;
        if (n + 1 < NN) d_h2[((size_t)g*NN + n + 1)*64 + tx] = a1;
        if (n + 2 < NN) d_h2[((size_t)g*NN + n + 2)*64 + tx] = a2;
        if (n + 3 < NN) d_h2[((size_t)g*NN + n + 3)*64 + tx] = a3;
    }
}

// ====== fin2: y2 + cu + colss/cssE ===========================================
__global__ __launch_bounds__(256) void k_fin2(const float* __restrict__ emb){
    int tid = threadIdx.x;
    __shared__ float cs[256];     // [m][col] col-SS partials: m0=emb, m1..3=g
    cs[tid] = 0.f;
    __syncthreads();
    int w = tid >> 5, lane = tid & 31;
    int row = (int)blockIdx.x*8 + w;
    bool valid = row < NN;
    bool item  = valid && (row >= NUSER);
    float o0 = 0.f, o1 = 0.f;
    if (valid){
        float a  = emb[(size_t)row*64 + lane];
        float b2 = emb[(size_t)row*64 + lane + 32];
        if (item){
            float inv = rsqrtf(wredsum(a*a + b2*b2));
            o0 = a*inv; o1 = b2*inv;
        } else {
            atomicAdd(&cs[lane],      a*a);
            atomicAdd(&cs[lane + 32], b2*b2);
        }
        #pragma unroll
        for (int g = 0; g < 3; g++){
            size_t base = ((size_t)g*RA + row)*64;
            float s0 = 0.f, s1 = 0.f;
            #pragma unroll
            for (int c = 0; c < NCH; c++){
                s0 += d_pacc[(size_t)c*CHS + base + lane];
                s1 += d_pacc[(size_t)c*CHS + base + lane + 32];
            }
            float ic = 1.f / fmaxf(d_cnt[g*RA + row], 1.f);
            float y0 = tanhf(ic*s0), y1 = tanhf(ic*s1);
            d_y2[((size_t)g*NN + row)*64 + lane]      = y0;
            d_y2[((size_t)g*NN + row)*64 + lane + 32] = y1;
            if (item){
                float inv = rsqrtf(wredsum(y0*y0 + y1*y1));
                o0 = fmaf(y0, inv, o0);
                o1 = fmaf(y1, inv, o1);
            } else {
                atomicAdd(&cs[(g+1)*64 + lane],      y0*y0);
                atomicAdd(&cs[(g+1)*64 + lane + 32], y1*y1);
            }
        }
        if (item){
            int r = row - NUSER;
            d_cu[r*64 + lane]      = 0.25f*o0;
            d_cu[r*64 + lane + 32] = 0.25f*o1;
        }
    }
    __syncthreads();
    float v = cs[tid];
    if (v != 0.f){
        int m = tid >> 6, c = tid & 63;
        if (m == 0) atomicAdd(&d_cssE[c], v);
        else        atomicAdd(&d_colss[(m-1)*64 + c], v);
    }
}

// ====== esmlp (x<128) + ci (128..329) + cnt-zero (330) ; BN sums fused =======
__global__ __launch_bounds__(256) void k_esmlp(const float* __restrict__ presc,
                                               const float* __restrict__ W,
                                               const float* __restrict__ b,
                                               const float* __restrict__ emb){
    int tid = threadIdx.x;
    if (blockIdx.x == 330){
        for (int j = tid; j < 3*RA; j += 256) d_cnt[j] = 0.f;
        return;
    }
    if (blockIdx.x >= 128){
        int i = (blockIdx.x - 128)*256 + tid;
        if (i < NUSER*64){
            int dcol = i & 63;
            float v = emb[i]                  * rsqrtf(d_cssE[dcol])
                    + d_y2[NN*64 + i]         * rsqrtf(d_colss[64  + dcol])
                    + d_y2[i]                 * rsqrtf(d_colss[      dcol])
                    + d_y2[2*NN*64 + i]       * rsqrtf(d_colss[128 + dcol]);
            d_ci[i] = 0.25f*v;
        }
        return;
    }
    __shared__ float4 cus[64*16];
    __shared__ float prs[16*68];
    __shared__ float Ws[64*68];
    __shared__ float ess[16*68];
    int tx = tid & 15, ty = tid >> 4;
    int n0 = blockIdx.x*16;
    for (int i = tid; i < 1024; i += 256)
        *reinterpret_cast<float4*>(&Ws[(i>>4)*68 + (i&15)*4]) =
            reinterpret_cast<const float4*>(W)[i];
    float4 acc = make_float4(0,0,0,0);
    float rs = 0.f;
    for (int k0 = 0; k0 < NITEM; k0 += 64){
        for (int i = tid; i < 1024; i += 256){
            int r = i>>4, c = i&15;
            int gk = k0 + r;
            cus[i] = (gk < NITEM) ? reinterpret_cast<const float4*>(d_cu)[gk*16 + c]
                                  : make_float4(0,0,0,0);
        }
        for (int i = tid; i < 1024; i += 256){
            int r = i>>6, c = i&63;
            int gk = k0 + c;
            prs[r*68 + c] = (gk < NITEM) ? presc[(size_t)(n0 + r)*NITEM + gk] : 0.f;
        }
        __syncthreads();
        int jm = min(64, NITEM - k0);
        for (int j = 0; j < jm; j++){
            float a = prs[ty*68 + j];
            rs += a;
            float4 cv = cus[j*16 + tx];
            acc.x = fmaf(a, cv.x, acc.x); acc.y = fmaf(a, cv.y, acc.y);
            acc.z = fmaf(a, cv.z, acc.z); acc.w = fmaf(a, cv.w, acc.w);
        }
        __syncthreads();
    }
    float inv = 1.f/rs;
    *reinterpret_cast<float4*>(&ess[ty*68 + tx*4]) =
        make_float4(acc.x*inv, acc.y*inv, acc.z*inv, acc.w*inv);
    __syncthreads();
    float4 o;
    float* op = &o.x;
    #pragma unroll
    for (int c = 0; c < 4; c++){
        int cc = tx*4 + c;
        float s = b[cc];
        #pragma unroll
        for (int k = 0; k < 64; k++) s = fmaf(ess[ty*68 + k], Ws[cc*68 + k], s);
        op[c] = s;
    }
    reinterpret_cast<float4*>(d_hb)[(size_t)(n0 + ty)*16 + tx] = o;
    // fused BN partial sums (reuse cus as scratch)
    float* red = reinterpret_cast<float*>(cus);
    red[ty*64 + tx*4 + 0] = o.x;
    red[ty*64 + tx*4 + 1] = o.y;
    red[ty*64 + tx*4 + 2] = o.z;
    red[ty*64 + tx*4 + 3] = o.w;
    __syncthreads();
    int rg = tid >> 6, c = tid & 63;
    float s = 0.f, s2 = 0.f;
    #pragma unroll
    for (int i = 0; i < 4; i++){
        float v = red[(rg*4 + i)*64 + c];
        s += v; s2 = fmaf(v, v, s2);
    }
    red[1024 + rg*64 + c] = s;
    red[1280 + rg*64 + c] = s2;
    __syncthreads();
    if (rg == 0){
        float S  = red[1024+c] + red[1088+c] + red[1152+c] + red[1216+c];
        float S2 = red[1280+c] + red[1344+c] + red[1408+c] + red[1472+c];
        atomicAdd(&d_bnsum[c],  S);
        atomicAdd(&d_bnsum2[c], S2);
    }
}

// ====== final: pre = relu(BN(hb)) @ c_i^T ; extra block zeros colss/cssE =====
__global__ __launch_bounds__(256) void k_final(float* __restrict__ out,
                                               const float* __restrict__ gamma,
                                               const float* __restrict__ beta){
    int tx = threadIdx.x, ty = threadIdx.y;
    int tid = ty*16 + tx;
    if (blockIdx.x == 13){
        if (blockIdx.y == 0){
            if (tid < 192) d_colss[tid] = 0.f;
            if (tid < 64)  d_cssE[tid]  = 0.f;
        }
        return;
    }
    int j0 = blockIdx.x*64;
    int n0 = blockIdx.y*64;
    __shared__ float cit[64*68];
    __shared__ float hsm[64*68];
    const float invB = 1.f/(float)BB;
    for (int i = tid; i < 1024; i += 256){
        int r = i >> 4, c4 = i & 15;
        float4 hv = reinterpret_cast<const float4*>(d_hb)[(size_t)(n0 + r)*16 + c4];
        int c = c4*4;
        float* hp = &hv.x;
        #pragma unroll
        for (int q = 0; q < 4; q++){
            int cc = c + q;
            float mu = d_bnsum[cc]*invB;
            float var = d_bnsum2[cc]*invB - mu*mu;
            float istd = rsqrtf(var + 1e-5f);
            hp[q] = fmaxf((hp[q] - mu)*istd*gamma[cc] + beta[cc], 0.f);
        }
        *reinterpret_cast<float4*>(&hsm[r*68 + c]) = hv;
        float4 v = (j0 + r < NUSER)
            ? reinterpret_cast<const float4*>(d_ci)[(size_t)(j0 + r)*16 + c4]
            : make_float4(0,0,0,0);
        cit[(c    )*68 + r] = v.x;
        cit[(c + 1)*68 + r] = v.y;
        cit[(c + 2)*68 + r] = v.z;
        cit[(c + 3)*68 + r] = v.w;
    }
    __syncthreads();
    unsigned long long acc[4][2] = {{0,0},{0,0},{0,0},{0,0}};
    #pragma unroll 8
    for (int k = 0; k < 64; k++){
        ulonglong2 cj = *reinterpret_cast<const ulonglong2*>(&cit[k*68 + tx*4]);
        #pragma unroll
        for (int r = 0; r < 4; r++){
            unsigned long long aa = dupf(hsm[(ty*4 + r)*68 + k]);
            fma2(acc[r][0], aa, cj.x);
            fma2(acc[r][1], aa, cj.y);
        }
    }
    #pragma unroll
    for (int r = 0; r < 4; r++){
        int n = n0 + ty*4 + r;
        int j = j0 + tx*4;
        float2 p0 = u2f(acc[r][0]);
        float2 p1 = u2f(acc[r][1]);
        float vals[4] = { p0.x, p0.y, p1.x, p1.y };
        #pragma unroll
        for (int c = 0; c < 4; c++)
            if (j + c < NUSER) out[(size_t)n*NUSER + j + c] = vals[c];
    }
}

// ---------------- launch -----------------------------------------------------
extern "C" void kernel_launch(void* const* d_in, const int* in_sizes, int n_in,
                              void* d_out, int out_size){
    const float* presc = (const float*)d_in[1];
    const float* emb   = (const float*)d_in[2];
    const float* W1    = (const float*)d_in[3];
    const float* b1    = (const float*)d_in[4];
    const float* W2    = (const float*)d_in[5];
    const float* b2    = (const float*)d_in[6];
    const float* mlpW  = (const float*)d_in[7];
    const float* mlpb  = (const float*)d_in[8];
    const float* gamma = (const float*)d_in[9];
    const float* beta  = (const float*)d_in[10];
    const int*   tg    = (const int*)d_in[11];
    const int*   sg1   = (const int*)d_in[12];
    const int*   sg2   = (const int*)d_in[13];
    int Et = in_sizes[11]/2;
    int E1 = in_sizes[12]/2;
    int E2 = in_sizes[13]/2;
    int Emax = Et > E1 ? Et : E1; if (E2 > Emax) Emax = E2;
    int EB = (Emax + 255)/256; if (EB < 39) EB = 39;
    float* out = (float*)d_out;

    // 1: A build (bf16 atomics) + h1 linear + bn-sum zero
    k_build3<<<dim3(EB, 4), 256>>>(tg, Et, sg1, E1, sg2, E2, emb, W1, b1);
    // 2: layer-1 aggregate (+ in-degree row sums)
    k_agg<1><<<dim3(RA/128, 3, NCH), 256>>>();
    // 3: tanh + layer-2 linear
    k_fin1<<<dim3(19, 3), 256>>>(W2, b2);
    // 4: layer-2 aggregate (+ re-zero A tiles for next replay)
    k_agg<2><<<dim3(RA/128, 3, NCH), 256>>>();
    // 5: tanh + cu + col-SS
    k_fin2<<<(NN + 7)/8, 256>>>(emb);
    // 6: pooled GEMM + MLP + BN sums, ci fusion, cnt zero
    k_esmlp<<<331, 256>>>(presc, mlpW, mlpb, emb);
    // 7: BN+relu+final GEMM (+ zero colss/cssE)
    k_final<<<dim3(14, BB/64), dim3(16,16)>>>(out, gamma, beta);
}

// round 13
// speedup vs baseline: 1.3642x; 1.3642x over previous
#include <cuda_runtime.h>
#include <math.h>

#define NN     1195
#define NUSER  805
#define NITEM  390
#define BB     2048
#define KPAD   1216           // A col stride (19 tiles of 64)
#define RA     1280           // A row alloc (10 blocks of 128)
#define MATSZ  (RA*KPAD)
#define NCH    19             // split-K chunks: ONE 64-wide k-tile each
#define CHS    (3*RA*64)      // pacc chunk stride (floats)

// ---------------- packed f32x2 helpers (Blackwell FFMA2) ---------------------
__device__ __forceinline__ void fma2(unsigned long long& d,
                                     unsigned long long a, unsigned long long b){
    asm("fma.rn.f32x2 %0, %1, %2, %0;" : "+l"(d) : "l"(a), "l"(b));
}
__device__ __forceinline__ unsigned long long dupf(float x){
    unsigned long long r;
    asm("mov.b64 %0, {%1, %1};" : "=l"(r) : "f"(x));
    return r;
}
__device__ __forceinline__ float2 u2f(unsigned long long x){
    float2 r;
    asm("mov.b64 {%0, %1}, %2;" : "=f"(r.x), "=f"(r.y) : "l"(x));
    return r;
}
__device__ __forceinline__ float wredsum(float s){
    #pragma unroll
    for (int off = 16; off; off >>= 1) s += __shfl_xor_sync(0xffffffffu, s, off);
    return s;
}

// ---------------- scratch (zero-initialized at module load) ------------------
__device__ float d_A[3*MATSZ];        // re-zeroed tile-by-tile inside k_agg<2>
__device__ float d_cnt[3*RA];         // zeroed in k_esmlp (end of run)
__device__ float d_h1[NN*64];
__device__ float d_h2[3*NN*64];
__device__ float d_pacc[NCH*CHS];     // fully overwritten each agg
__device__ float d_y2[3*NN*64];
__device__ float d_cu[NITEM*64];
__device__ float d_ci[NUSER*64];
__device__ float d_colss[3*64];       // zeroed in k_final (end of run)
__device__ float d_cssE[64];          // zeroed in k_final (end of run)
__device__ float d_hb[BB*64];
__device__ float d_bnsum[64];         // zeroed in k_build3 (start of run)
__device__ float d_bnsum2[64];

// ====== launch 1: build A (float atomics) + lin1 + bn zero ===================
__global__ __launch_bounds__(256,3) void k_build3(
        const int* __restrict__ e0, int E0,
        const int* __restrict__ e1, int E1,
        const int* __restrict__ e2, int E2,
        const float* __restrict__ x, const float* __restrict__ W,
        const float* __restrict__ b){
    int g = blockIdx.y;
    int tid = threadIdx.x;
    if (g < 3){
        const int* e = (g == 0) ? e0 : (g == 1) ? e1 : e2;
        int E       = (g == 0) ? E0 : (g == 1) ? E1 : E2;
        int i = blockIdx.x*256 + tid;
        if (i < E){
            int s = e[i];
            int d = e[E + i];
            atomicAdd(&d_A[(size_t)g*MATSZ + (size_t)d*KPAD + s], 1.0f);
        }
        return;
    }
    // g == 3 : auxiliary work
    if (blockIdx.x == 38){
        if (tid < 64){ d_bnsum[tid] = 0.f; d_bnsum2[tid] = 0.f; }
        return;
    }
    if (blockIdx.x > 38) return;
    // lin1: 32 rows per block
    __shared__ float Ws[64*68];
    __shared__ float xs[32*68];
    int n0 = blockIdx.x*32;
    for (int i = tid; i < 1024; i += 256)
        *reinterpret_cast<float4*>(&Ws[(i>>4)*68 + (i&15)*4]) =
            reinterpret_cast<const float4*>(W)[i];
    for (int i = tid; i < 512; i += 256){
        int r = i>>4, c4 = i&15;
        float4 v = (n0 + r < NN) ? reinterpret_cast<const float4*>(x)[(n0+r)*16 + c4]
                                 : make_float4(0,0,0,0);
        *reinterpret_cast<float4*>(&xs[r*68 + c4*4]) = v;
    }
    __syncthreads();
    int tx = tid & 63, ty = tid >> 6;
    float bb = b[tx];
    #pragma unroll
    for (int i0 = 0; i0 < 8; i0 += 2){
        int rl = ty*8 + i0;
        float a0 = bb, a1 = bb;
        #pragma unroll
        for (int k = 0; k < 64; k += 4){
            float4 w  = *reinterpret_cast<const float4*>(&Ws[tx*68 + k]);
            float4 x0 = *reinterpret_cast<const float4*>(&xs[(rl  )*68 + k]);
            float4 x1 = *reinterpret_cast<const float4*>(&xs[(rl+1)*68 + k]);
            a0 = fmaf(x0.x,w.x,a0); a0 = fmaf(x0.y,w.y,a0);
            a0 = fmaf(x0.z,w.z,a0); a0 = fmaf(x0.w,w.w,a0);
            a1 = fmaf(x1.x,w.x,a1); a1 = fmaf(x1.y,w.y,a1);
            a1 = fmaf(x1.z,w.z,a1); a1 = fmaf(x1.w,w.w,a1);
        }
        int n = n0 + rl;
        if (n     < NN) d_h1[(size_t)(n  )*64 + tx] = a0;
        if (n + 1 < NN) d_h1[(size_t)(n+1)*64 + tx] = a1;
    }
}

// ====== agg: pacc[t] = A_tile @ h (128-row x 64-col tile, 128 threads) =======
// 8 rows x 8 cols per thread: per warp per j, 16 LDS.128-wavefronts serve 32
// warp-FFMA2 (0.5 wf/FFMA2 vs 0.75 in the 256-thread/4-row version).
// All 8 tx threads of a row-group read the SAME A values -> rsum is already
// the complete tile-row sum; tx==0 adds it directly (layer 1 only).
// Layer 2 re-zeroes its own gmem A tile (each tile read exactly once there).
template<int LAYER>
__global__ __launch_bounds__(128) void k_agg(){
    const int g = blockIdx.y, t = blockIdx.z;
    float* Anc = d_A + (size_t)g*MATSZ;
    const float* A = Anc;
    const float* h = (LAYER == 1) ? d_h1 : d_h2 + (size_t)g*NN*64;
    __shared__ float As[128*64];   // xor-swizzled by ((row>>3)&3)<<3
    __shared__ float hs[64*64];
    int tid = threadIdx.x;
    int tx = tid & 7;              // 8 col-groups of 8
    int ty = tid >> 3;             // 0..15, 8 rows each
    int n0 = blockIdx.x*128;
    int k0 = t*64;
    // stage A: 128x64 floats = 32KB
    #pragma unroll
    for (int i = tid; i < 2048; i += 128){
        int r = i >> 4, c4 = i & 15;
        float4 v = *reinterpret_cast<const float4*>(
                      &A[(size_t)(n0 + r)*KPAD + k0 + c4*4]);
        int sw = ((r>>3) & 3) << 3;
        *reinterpret_cast<float4*>(&As[r*64 + ((c4*4) ^ sw)]) = v;
    }
    // stage h: 64x64 floats = 16KB
    #pragma unroll
    for (int i = tid; i < 1024; i += 128){
        int jr = i >> 4, c4 = i & 15;
        int gk = k0 + jr;
        float4 v = (gk < NN) ? reinterpret_cast<const float4*>(h)[gk*16 + c4]
                             : make_float4(0,0,0,0);
        *reinterpret_cast<float4*>(&hs[jr*64 + c4*4]) = v;
    }
    __syncthreads();
    if (LAYER == 2){
        // A tile is in smem now; re-zero the gmem copy for the next replay.
        float4 z = make_float4(0,0,0,0);
        #pragma unroll
        for (int i = tid; i < 2048; i += 128){
            int r = i >> 4, c4 = i & 15;
            *reinterpret_cast<float4*>(&Anc[(size_t)(n0 + r)*KPAD + k0 + c4*4]) = z;
        }
    }
    unsigned long long acc[8][4];
    #pragma unroll
    for (int r = 0; r < 8; r++){
        acc[r][0] = 0ull; acc[r][1] = 0ull; acc[r][2] = 0ull; acc[r][3] = 0ull;
    }
    float rsum[8] = {0,0,0,0,0,0,0,0};
    int s8 = (ty & 3) << 3;        // == ((row>>3)&3)<<3 for rows ty*8..ty*8+7
    const float* Arow = &As[(ty*8)*64];
    #pragma unroll 2
    for (int j4 = 0; j4 < 64; j4 += 4){
        int jc = j4 ^ s8;          // 8-aligned: (j4+i)^s8 == (j4^s8)+i, i<4
        float4 Av[8];
        #pragma unroll
        for (int r = 0; r < 8; r++)
            Av[r] = *reinterpret_cast<const float4*>(&Arow[r*64 + jc]);
        if (LAYER == 1){
            #pragma unroll
            for (int r = 0; r < 8; r++)
                rsum[r] += Av[r].x + Av[r].y + Av[r].z + Av[r].w;
        }
        #pragma unroll
        for (int jj = 0; jj < 4; jj++){
            int j = j4 + jj;
            ulonglong2 h0 = *reinterpret_cast<const ulonglong2*>(&hs[j*64 + tx*8]);
            ulonglong2 h1 = *reinterpret_cast<const ulonglong2*>(&hs[j*64 + tx*8 + 4]);
            #pragma unroll
            for (int r = 0; r < 8; r++){
                const float* ap = &Av[r].x;
                unsigned long long a = dupf(ap[jj]);
                fma2(acc[r][0], a, h0.x); fma2(acc[r][1], a, h0.y);
                fma2(acc[r][2], a, h1.x); fma2(acc[r][3], a, h1.y);
            }
        }
    }
    float* p = d_pacc + (size_t)t*CHS + (size_t)g*RA*64;
    #pragma unroll
    for (int r = 0; r < 8; r++){
        size_t row = n0 + ty*8 + r;
        ulonglong2 v0; v0.x = acc[r][0]; v0.y = acc[r][1];
        ulonglong2 v1; v1.x = acc[r][2]; v1.y = acc[r][3];
        *reinterpret_cast<ulonglong2*>(&p[row*64 + tx*8    ]) = v0;
        *reinterpret_cast<ulonglong2*>(&p[row*64 + tx*8 + 4]) = v1;
    }
    if (LAYER == 1 && tx == 0){
        #pragma unroll
        for (int r = 0; r < 8; r++)
            atomicAdd(&d_cnt[g*RA + n0 + ty*8 + r], rsum[r]);
    }
}

// ====== fin1: y1 = tanh(ic*sum(pacc)); h2 = y1 @ W2^T + b2 ===================
__global__ __launch_bounds__(256) void k_fin1(const float* __restrict__ W2,
                                              const float* __restrict__ b2){
    int g = blockIdx.y;
    int n0 = blockIdx.x*64;
    __shared__ float Ws[64*68];
    __shared__ float ys[64*68];
    int tid = threadIdx.x;
    for (int i = tid; i < 1024; i += 256){
        int r = i>>4, c4 = i&15;
        *reinterpret_cast<float4*>(&Ws[r*68 + c4*4]) =
            reinterpret_cast<const float4*>(W2)[i];
        size_t off = ((size_t)g*RA + n0 + r)*16 + c4;
        float4 s = reinterpret_cast<const float4*>(d_pacc)[off];
        #pragma unroll
        for (int c = 1; c < NCH; c++){
            float4 v = reinterpret_cast<const float4*>(d_pacc)[(size_t)c*(CHS/4) + off];
            s.x += v.x; s.y += v.y; s.z += v.z; s.w += v.w;
        }
        float ic = 1.f / fmaxf(d_cnt[g*RA + n0 + r], 1.f);
        float4 o;
        o.x = tanhf(ic*s.x); o.y = tanhf(ic*s.y);
        o.z = tanhf(ic*s.z); o.w = tanhf(ic*s.w);
        *reinterpret_cast<float4*>(&ys[r*68 + c4*4]) = o;
    }
    __syncthreads();
    int tx = tid & 63, ty = tid >> 6;
    float bb = b2[tx];
    #pragma unroll
    for (int i0 = 0; i0 < 16; i0 += 4){
        int rl = ty*16 + i0;
        float a0 = bb, a1 = bb, a2 = bb, a3 = bb;
        #pragma unroll
        for (int k = 0; k < 64; k += 4){
            float4 w  = *reinterpret_cast<const float4*>(&Ws[tx*68 + k]);
            float4 x0 = *reinterpret_cast<const float4*>(&ys[(rl  )*68 + k]);
            float4 x1 = *reinterpret_cast<const float4*>(&ys[(rl+1)*68 + k]);
            float4 x2 = *reinterpret_cast<const float4*>(&ys[(rl+2)*68 + k]);
            float4 x3 = *reinterpret_cast<const float4*>(&ys[(rl+3)*68 + k]);
            a0 = fmaf(x0.x,w.x,a0); a0 = fmaf(x0.y,w.y,a0);
            a0 = fmaf(x0.z,w.z,a0); a0 = fmaf(x0.w,w.w,a0);
            a1 = fmaf(x1.x,w.x,a1); a1 = fmaf(x1.y,w.y,a1);
            a1 = fmaf(x1.z,w.z,a1); a1 = fmaf(x1.w,w.w,a1);
            a2 = fmaf(x2.x,w.x,a2); a2 = fmaf(x2.y,w.y,a2);
            a2 = fmaf(x2.z,w.z,a2); a2 = fmaf(x2.w,w.w,a2);
            a3 = fmaf(x3.x,w.x,a3); a3 = fmaf(x3.y,w.y,a3);
            a3 = fmaf(x3.z,w.z,a3); a3 = fmaf(x3.w,w.w,a3);
        }
        int n = n0 + rl;
        if (n     < NN) d_h2[((size_t)g*NN + n    )*64 + tx] = a0;
        if (n + 1 < NN) d_h2[((size_t)g*NN + n + 1)*64 + tx] = a1;
        if (n + 2 < NN) d_h2[((size_t)g*NN + n + 2)*64 + tx] = a2;
        if (n + 3 < NN) d_h2[((size_t)g*NN + n + 3)*64 + tx] = a3;
    }
}

// ====== fin2: y2 + cu + colss/cssE ===========================================
__global__ __launch_bounds__(256) void k_fin2(const float* __restrict__ emb){
    int tid = threadIdx.x;
    __shared__ float cs[256];     // [m][col] col-SS partials: m0=emb, m1..3=g
    cs[tid] = 0.f;
    __syncthreads();
    int w = tid >> 5, lane = tid & 31;
    int row = (int)blockIdx.x*8 + w;
    bool valid = row < NN;
    bool item  = valid && (row >= NUSER);
    float o0 = 0.f, o1 = 0.f;
    if (valid){
        float a  = emb[(size_t)row*64 + lane];
        float b2 = emb[(size_t)row*64 + lane + 32];
        if (item){
            float inv = rsqrtf(wredsum(a*a + b2*b2));
            o0 = a*inv; o1 = b2*inv;
        } else {
            atomicAdd(&cs[lane],      a*a);
            atomicAdd(&cs[lane + 32], b2*b2);
        }
        #pragma unroll
        for (int g = 0; g < 3; g++){
            size_t base = ((size_t)g*RA + row)*64;
            float s0 = 0.f, s1 = 0.f;
            #pragma unroll
            for (int c = 0; c < NCH; c++){
                s0 += d_pacc[(size_t)c*CHS + base + lane];
                s1 += d_pacc[(size_t)c*CHS + base + lane + 32];
            }
            float ic = 1.f / fmaxf(d_cnt[g*RA + row], 1.f);
            float y0 = tanhf(ic*s0), y1 = tanhf(ic*s1);
            d_y2[((size_t)g*NN + row)*64 + lane]      = y0;
            d_y2[((size_t)g*NN + row)*64 + lane + 32] = y1;
            if (item){
                float inv = rsqrtf(wredsum(y0*y0 + y1*y1));
                o0 = fmaf(y0, inv, o0);
                o1 = fmaf(y1, inv, o1);
            } else {
                atomicAdd(&cs[(g+1)*64 + lane],      y0*y0);
                atomicAdd(&cs[(g+1)*64 + lane + 32], y1*y1);
            }
        }
        if (item){
            int r = row - NUSER;
            d_cu[r*64 + lane]      = 0.25f*o0;
            d_cu[r*64 + lane + 32] = 0.25f*o1;
        }
    }
    __syncthreads();
    float v = cs[tid];
    if (v != 0.f){
        int m = tid >> 6, c = tid & 63;
        if (m == 0) atomicAdd(&d_cssE[c], v);
        else        atomicAdd(&d_colss[(m-1)*64 + c], v);
    }
}

// ====== esmlp (x<128) + ci (128..329) + cnt-zero (330) ; BN sums fused =======
__global__ __launch_bounds__(256) void k_esmlp(const float* __restrict__ presc,
                                               const float* __restrict__ W,
                                               const float* __restrict__ b,
                                               const float* __restrict__ emb){
    int tid = threadIdx.x;
    if (blockIdx.x == 330){
        for (int j = tid; j < 3*RA; j += 256) d_cnt[j] = 0.f;
        return;
    }
    if (blockIdx.x >= 128){
        int i = (blockIdx.x - 128)*256 + tid;
        if (i < NUSER*64){
            int dcol = i & 63;
            float v = emb[i]                  * rsqrtf(d_cssE[dcol])
                    + d_y2[NN*64 + i]         * rsqrtf(d_colss[64  + dcol])
                    + d_y2[i]                 * rsqrtf(d_colss[      dcol])
                    + d_y2[2*NN*64 + i]       * rsqrtf(d_colss[128 + dcol]);
            d_ci[i] = 0.25f*v;
        }
        return;
    }
    __shared__ float4 cus[64*16];
    __shared__ float prs[16*68];
    __shared__ float Ws[64*68];
    __shared__ float ess[16*68];
    int tx = tid & 15, ty = tid >> 4;
    int n0 = blockIdx.x*16;
    for (int i = tid; i < 1024; i += 256)
        *reinterpret_cast<float4*>(&Ws[(i>>4)*68 + (i&15)*4]) =
            reinterpret_cast<const float4*>(W)[i];
    float4 acc = make_float4(0,0,0,0);
    float rs = 0.f;
    for (int k0 = 0; k0 < NITEM; k0 += 64){
        for (int i = tid; i < 1024; i += 256){
            int r = i>>4, c = i&15;
            int gk = k0 + r;
            cus[i] = (gk < NITEM) ? reinterpret_cast<const float4*>(d_cu)[gk*16 + c]
                                  : make_float4(0,0,0,0);
        }
        for (int i = tid; i < 1024; i += 256){
            int r = i>>6, c = i&63;
            int gk = k0 + c;
            prs[r*68 + c] = (gk < NITEM) ? presc[(size_t)(n0 + r)*NITEM + gk] : 0.f;
        }
        __syncthreads();
        int jm = min(64, NITEM - k0);
        for (int j = 0; j < jm; j++){
            float a = prs[ty*68 + j];
            rs += a;
            float4 cv = cus[j*16 + tx];
            acc.x = fmaf(a, cv.x, acc.x); acc.y = fmaf(a, cv.y, acc.y);
            acc.z = fmaf(a, cv.z, acc.z); acc.w = fmaf(a, cv.w, acc.w);
        }
        __syncthreads();
    }
    float inv = 1.f/rs;
    *reinterpret_cast<float4*>(&ess[ty*68 + tx*4]) =
        make_float4(acc.x*inv, acc.y*inv, acc.z*inv, acc.w*inv);
    __syncthreads();
    float4 o;
    float* op = &o.x;
    #pragma unroll
    for (int c = 0; c < 4; c++){
        int cc = tx*4 + c;
        float s = b[cc];
        #pragma unroll
        for (int k = 0; k < 64; k++) s = fmaf(ess[ty*68 + k], Ws[cc*68 + k], s);
        op[c] = s;
    }
    reinterpret_cast<float4*>(d_hb)[(size_t)(n0 + ty)*16 + tx] = o;
    // fused BN partial sums (reuse cus as scratch)
    float* red = reinterpret_cast<float*>(cus);
    red[ty*64 + tx*4 + 0] = o.x;
    red[ty*64 + tx*4 + 1] = o.y;
    red[ty*64 + tx*4 + 2] = o.z;
    red[ty*64 + tx*4 + 3] = o.w;
    __syncthreads();
    int rg = tid >> 6, c = tid & 63;
    float s = 0.f, s2 = 0.f;
    #pragma unroll
    for (int i = 0; i < 4; i++){
        float v = red[(rg*4 + i)*64 + c];
        s += v; s2 = fmaf(v, v, s2);
    }
    red[1024 + rg*64 + c] = s;
    red[1280 + rg*64 + c] = s2;
    __syncthreads();
    if (rg == 0){
        float S  = red[1024+c] + red[1088+c] + red[1152+c] + red[1216+c];
        float S2 = red[1280+c] + red[1344+c] + red[1408+c] + red[1472+c];
        atomicAdd(&d_bnsum[c],  S);
        atomicAdd(&d_bnsum2[c], S2);
    }
}

// ====== final: pre = relu(BN(hb)) @ c_i^T ; extra block zeros colss/cssE =====
__global__ __launch_bounds__(256) void k_final(float* __restrict__ out,
                                               const float* __restrict__ gamma,
                                               const float* __restrict__ beta){
    int tx = threadIdx.x, ty = threadIdx.y;
    int tid = ty*16 + tx;
    if (blockIdx.x == 13){
        if (blockIdx.y == 0){
            if (tid < 192) d_colss[tid] = 0.f;
            if (tid < 64)  d_cssE[tid]  = 0.f;
        }
        return;
    }
    int j0 = blockIdx.x*64;
    int n0 = blockIdx.y*64;
    __shared__ float cit[64*68];
    __shared__ float hsm[64*68];
    const float invB = 1.f/(float)BB;
    for (int i = tid; i < 1024; i += 256){
        int r = i >> 4, c4 = i & 15;
        float4 hv = reinterpret_cast<const float4*>(d_hb)[(size_t)(n0 + r)*16 + c4];
        int c = c4*4;
        float* hp = &hv.x;
        #pragma unroll
        for (int q = 0; q < 4; q++){
            int cc = c + q;
            float mu = d_bnsum[cc]*invB;
            float var = d_bnsum2[cc]*invB - mu*mu;
            float istd = rsqrtf(var + 1e-5f);
            hp[q] = fmaxf((hp[q] - mu)*istd*gamma[cc] + beta[cc], 0.f);
        }
        *reinterpret_cast<float4*>(&hsm[r*68 + c]) = hv;
        float4 v = (j0 + r < NUSER)
            ? reinterpret_cast<const float4*>(d_ci)[(size_t)(j0 + r)*16 + c4]
            : make_float4(0,0,0,0);
        cit[(c    )*68 + r] = v.x;
        cit[(c + 1)*68 + r] = v.y;
        cit[(c + 2)*68 + r] = v.z;
        cit[(c + 3)*68 + r] = v.w;
    }
    __syncthreads();
    unsigned long long acc[4][2] = {{0,0},{0,0},{0,0},{0,0}};
    #pragma unroll 8
    for (int k = 0; k < 64; k++){
        ulonglong2 cj = *reinterpret_cast<const ulonglong2*>(&cit[k*68 + tx*4]);
        #pragma unroll
        for (int r = 0; r < 4; r++){
            unsigned long long aa = dupf(hsm[(ty*4 + r)*68 + k]);
            fma2(acc[r][0], aa, cj.x);
            fma2(acc[r][1], aa, cj.y);
        }
    }
    #pragma unroll
    for (int r = 0; r < 4; r++){
        int n = n0 + ty*4 + r;
        int j = j0 + tx*4;
        float2 p0 = u2f(acc[r][0]);
        float2 p1 = u2f(acc[r][1]);
        float vals[4] = { p0.x, p0.y, p1.x, p1.y };
        #pragma unroll
        for (int c = 0; c < 4; c++)
            if (j + c < NUSER) out[(size_t)n*NUSER + j + c] = vals[c];
    }
}

// ---------------- launch -----------------------------------------------------
extern "C" void kernel_launch(void* const* d_in, const int* in_sizes, int n_in,
                              void* d_out, int out_size){
    const float* presc = (const float*)d_in[1];
    const float* emb   = (const float*)d_in[2];
    const float* W1    = (const float*)d_in[3];
    const float* b1    = (const float*)d_in[4];
    const float* W2    = (const float*)d_in[5];
    const float* b2    = (const float*)d_in[6];
    const float* mlpW  = (const float*)d_in[7];
    const float* mlpb  = (const float*)d_in[8];
    const float* gamma = (const float*)d_in[9];
    const float* beta  = (const float*)d_in[10];
    const int*   tg    = (const int*)d_in[11];
    const int*   sg1   = (const int*)d_in[12];
    const int*   sg2   = (const int*)d_in[13];
    int Et = in_sizes[11]/2;
    int E1 = in_sizes[12]/2;
    int E2 = in_sizes[13]/2;
    int Emax = Et > E1 ? Et : E1; if (E2 > Emax) Emax = E2;
    int EB = (Emax + 255)/256; if (EB < 39) EB = 39;
    float* out = (float*)d_out;

    // 1: A build (float atomics) + h1 linear + bn-sum zero
    k_build3<<<dim3(EB, 4), 256>>>(tg, Et, sg1, E1, sg2, E2, emb, W1, b1);
    // 2: layer-1 aggregate (+ in-degree row sums)
    k_agg<1><<<dim3(RA/128, 3, NCH), 128>>>();
    // 3: tanh + layer-2 linear
    k_fin1<<<dim3(19, 3), 256>>>(W2, b2);
    // 4: layer-2 aggregate (+ re-zero A tiles for next replay)
    k_agg<2><<<dim3(RA/128, 3, NCH), 128>>>();
    // 5: tanh + cu + col-SS
    k_fin2<<<(NN + 7)/8, 256>>>(emb);
    // 6: pooled GEMM + MLP + BN sums, ci fusion, cnt zero
    k_esmlp<<<331, 256>>>(presc, mlpW, mlpb, emb);
    // 7: BN+relu+final GEMM (+ zero colss/cssE)
    k_final<<<dim3(14, BB/64), dim3(16,16)>>>(out, gamma, beta);
}